// round 15
// baseline (speedup 1.0000x reference)
#include <cuda_runtime.h>
#include <cstddef>

// Problem constants
#define BB    4096
#define NXD   64
#define NUD   16
#define HH    50
#define HIDD  256
#define ZD    80
#define W1STRIDE 260
#define W2STRIDE 260

// Output layout
#define OFF_U      0
#define OFF_XTRAJ  (BB*NUD)
#define OFF_XPRED  (OFF_XTRAJ + BB*(HH+1)*NXD)
#define OFF_GX     (OFF_XPRED + BB*HH*NXD)
#define OFF_GU     (OFF_GX + BB*HH*NXD)

// smem layout (float offsets). Total 57,920 floats = 231,680 B
#define SM_W1    0                        // [80][260] m-permuted
#define SM_W2T   (SM_W1 + ZD*W1STRIDE)    // [64][260] m-permuted
#define SM_XD    (SM_W2T + NXD*W2STRIDE)  // float2 [32 rows][64] dup x
#define SM_TALL  (SM_XD + 32*64*2)        // float [32 rows][256] h-partials -> t
#define SM_GALL  (SM_TALL + 32*256)       // float [32 rows][256] gh (row lr+4 [0:128] = u buf)
#define SM_TOTAL_F (SM_GALL + 32*256)

#define NT 256   // 8 warps: 4 pairs (E = warp p, O = warp p+4), 8 rows per pair

typedef unsigned long long ull;

__device__ float g_u9[BB * HH * NUD];

union F2U { ull u; float2 f; };

__device__ __forceinline__ ull fma2(ull a, ull b, ull c) {
    ull d;
    asm("fma.rn.f32x2 %0, %1, %2, %3;" : "=l"(d) : "l"(a), "l"(b), "l"(c));
    return d;
}
__device__ __forceinline__ ull mul2(ull a, ull b) {
    ull d;
    asm("mul.rn.f32x2 %0, %1, %2;" : "=l"(d) : "l"(a), "l"(b));
    return d;
}
__device__ __forceinline__ ull add2(ull a, ull b) {
    ull d;
    asm("add.rn.f32x2 %0, %1, %2;" : "=l"(d) : "l"(a), "l"(b));
    return d;
}
// tanh(x) = 1 - 2/(exp2(2*log2e*x)+1)
__device__ __forceinline__ float tanhfast(float x) {
    float e, r;
    asm("ex2.approx.f32 %0, %1;" : "=f"(e) : "f"(x * 2.885390081777927f));
    asm("rcp.approx.f32 %0, %1;" : "=f"(r) : "f"(e + 1.0f));
    return fmaf(-2.0f, r, 1.0f);
}
__device__ __forceinline__ ull dup2(float v) {
    F2U p; p.f.x = v; p.f.y = v; return p.u;
}
// m-permutation: lane l owns m-pairs (64j+2l, 64j+2l+1); j01/j23 groups are
// 16B-contiguous at 4l and 128+4l.
__device__ __forceinline__ int permpos(int m) {
    int j = m >> 6, l = (m & 63) >> 1, e = m & 1;
    return 128 * (j >> 1) + 4 * l + 2 * (j & 1) + e;
}

// ---------------------------------------------------------------------------
__global__ void prep_kernel(const float4* __restrict__ noise4,
                            const int* __restrict__ nit_p,
                            float* __restrict__ out_u) {
    const int TOT4 = BB * HH * NUD / 4;
    int idx = blockIdx.x * blockDim.x + threadIdx.x;
    if (idx >= TOT4) return;
    int nit = *nit_p;
    float4 s = make_float4(0.f, 0.f, 0.f, 0.f);
    for (int it = 0; it < nit - 1; ++it) {
        float4 v = noise4[(size_t)it * TOT4 + idx];
        s.x += v.x; s.y += v.y; s.z += v.z; s.w += v.w;
    }
    float4 u9 = make_float4(0.001f * s.x, 0.001f * s.y,
                            0.001f * s.z, 0.001f * s.w);
    ((float4*)g_u9)[idx] = u9;
    int base = 4 * idx;
    int rem = base % (HH * NUD);
    if (rem < NUD) {
        float4 nl = noise4[(size_t)(nit - 1) * TOT4 + idx];
        int b = base / (HH * NUD);
        float* o = out_u + b * NUD + rem;
        o[0] = u9.x + 0.001f * nl.x;
        o[1] = u9.y + 0.001f * nl.y;
        o[2] = u9.z + 0.001f * nl.z;
        o[3] = u9.w + 0.001f * nl.w;
    }
}

// ---------------------------------------------------------------------------
// grid 128 x 256. 4 pairs of warps; pair p = (E=warp p, O=warp p+4), one E and
// one O per SMSP, 8 rows per pair.
// Per step: [A] O stages u; E,O compute K-split GEMV1 partials (E: i<40,
// O: i>=40) for all 8 rows; partial-exchange via tall; [sync1] E finalizes
// rows 0-3 (tanh -> t,gh), O rows 4-7; [sync2] E: GEMV2 all 8 rows,
// O: grad all 8 rows (same step); [syncA].
// ---------------------------------------------------------------------------
__global__ __launch_bounds__(NT, 1)
void mpc_kernel(const float* __restrict__ x0,
                const float* __restrict__ W1g,   // [80,256]
                const float* __restrict__ b1g,   // [256]
                const float* __restrict__ W2g,   // [256,64]
                float* __restrict__ out_xtraj,
                float* __restrict__ out_xpred,
                float* __restrict__ out_gx,
                float* __restrict__ out_gu) {
    extern __shared__ float smem[];
    float*  W1s  = smem + SM_W1;
    float*  W2Ts = smem + SM_W2T;
    float2* xd   = (float2*)(smem + SM_XD);
    float*  tall = smem + SM_TALL;
    float*  gall = smem + SM_GALL;

    const int tid = threadIdx.x;

    // ---- Stage weights (m-permuted) + c2 scratch (permuted, in tall) ----
    for (int idx = tid; idx < ZD * HIDD; idx += NT) {
        int i = idx >> 8, m = idx & 255;
        W1s[i * W1STRIDE + permpos(m)] = W1g[idx];
    }
    for (int idx = tid; idx < HIDD * NXD; idx += NT) {
        int m = idx >> 6, c = idx & 63;
        W2Ts[c * W2STRIDE + permpos(m)] = W2g[idx];
    }
    {
        int m = tid;
        float s = 0.f;
        #pragma unroll 8
        for (int j = 0; j < NXD; ++j) s += W2g[m * NXD + j];
        tall[permpos(m)] = 0.1f * s;   // c2 scratch (permuted)
    }
    __syncthreads();

    const int  w    = tid >> 5, lane = tid & 31;
    const bool isE  = (w < 4);
    const int  p    = w & 3;
    const int  lr   = p * 8;
    const int  b0   = blockIdx.x * 32 + lr;
    const int  m2   = 2 * lane;
    const int  ui   = lane & 15;
    const bool lo16 = (lane < 16);

    // constants (both roles need c2 for tanh/gh; E needs b1)
    ull b1p[4], c2p[4], nc2p[4];
    #pragma unroll
    for (int j = 0; j < 4; ++j) {
        b1p[j] = isE ? *(const ull*)&b1g[64 * j + m2] : 0ull;
        F2U c;
        c.u = *(const ull*)&tall[128 * (j >> 1) + 4 * lane + 2 * (j & 1)];
        c2p[j] = c.u;
        F2U n; n.f.x = -c.f.x; n.f.y = -c.f.y;
        nc2p[j] = n.u;
    }
    __syncthreads();   // c2 scratch consumed (tall row 0 gets reused)

    // init xd + x_traj[:,0,:]  (E: rows 0-3, O: rows 4-7)
    {
        int rbase = isE ? 0 : 4;
        #pragma unroll
        for (int r = 0; r < 4; ++r) {
            int row = rbase + r;
            int b = b0 + row;
            float xa = x0[b * NXD + lane];
            float xb = x0[b * NXD + 32 + lane];
            xd[(lr + row) * 64 + lane]      = make_float2(xa, xa);
            xd[(lr + row) * 64 + 32 + lane] = make_float2(xb, xb);
            size_t base = (size_t)b * (HH + 1) * NXD;
            out_xtraj[base + lane]      = xa;
            out_xtraj[base + 32 + lane] = xb;
        }
    }

    // O: prefetch u for step 0 (4 values: rows 2v+(lane>>4), col ui)
    float up[4];
    if (!isE) {
        #pragma unroll
        for (int v = 0; v < 4; ++v)
            up[v] = g_u9[(size_t)(b0 + 2 * v + (lane >> 4)) * HH * NUD + ui];
    }
    float* ubuf = gall + (lr + 4) * 256;   // [8 rows][16] plain u (aliases gh row 4)
    __syncthreads();   // xd ready for step 0

    const ulonglong2* w2a = (const ulonglong2*)&W2Ts[lane * W2STRIDE];
    const ulonglong2* w2b = (const ulonglong2*)&W2Ts[(lane + 32) * W2STRIDE];
    const ulonglong2* wia = (const ulonglong2*)&W1s[lane * W1STRIDE];
    const ulonglong2* wib = (const ulonglong2*)&W1s[(32 + lane) * W1STRIDE];
    const ulonglong2* wic = (const ulonglong2*)&W1s[(64 + ui) * W1STRIDE];

    for (int k = 0; k < HH; ++k) {
        ull hp[8][4];

        if (isE) {
            // ---- E: GEMV1 partial over i=0..39 (x), all 8 rows ----
            #pragma unroll
            for (int r = 0; r < 8; ++r)
                #pragma unroll
                for (int j = 0; j < 4; ++j) hp[r][j] = b1p[j];
            #pragma unroll 4
            for (int i = 0; i < 40; i += 2) {
                const float* w0 = &W1s[i * W1STRIDE];
                const float* w1 = &W1s[(i + 1) * W1STRIDE];
                ulonglong2 wA = *(const ulonglong2*)&w0[4 * lane];
                ulonglong2 wB = *(const ulonglong2*)&w0[128 + 4 * lane];
                ulonglong2 wC = *(const ulonglong2*)&w1[4 * lane];
                ulonglong2 wD = *(const ulonglong2*)&w1[128 + 4 * lane];
                #pragma unroll
                for (int r = 0; r < 8; ++r) {
                    ulonglong2 zv = *(const ulonglong2*)&xd[(lr + r) * 64 + i];
                    hp[r][0] = fma2(zv.x, wA.x, hp[r][0]);
                    hp[r][1] = fma2(zv.x, wA.y, hp[r][1]);
                    hp[r][2] = fma2(zv.x, wB.x, hp[r][2]);
                    hp[r][3] = fma2(zv.x, wB.y, hp[r][3]);
                    hp[r][0] = fma2(zv.y, wC.x, hp[r][0]);
                    hp[r][1] = fma2(zv.y, wC.y, hp[r][1]);
                    hp[r][2] = fma2(zv.y, wD.x, hp[r][2]);
                    hp[r][3] = fma2(zv.y, wD.y, hp[r][3]);
                }
            }
            // write partials for rows 4-7 (O finalizes those)
            #pragma unroll
            for (int r = 4; r < 8; ++r) {
                int base = (lr + r) * 256;
                ulonglong2 s01, s23;
                s01.x = hp[r][0]; s01.y = hp[r][1];
                s23.x = hp[r][2]; s23.y = hp[r][3];
                *(ulonglong2*)&tall[base + 4 * lane]       = s01;
                *(ulonglong2*)&tall[base + 128 + 4 * lane] = s23;
            }
        } else {
            // ---- O: stage u (plain), GEMV1 partial over i=40..79 ----
            #pragma unroll
            for (int v = 0; v < 4; ++v)
                ubuf[(2 * v + (lane >> 4)) * 16 + ui] = up[v];
            __syncwarp();
            if (k + 1 < HH) {
                #pragma unroll
                for (int v = 0; v < 4; ++v)
                    up[v] = g_u9[(size_t)(b0 + 2 * v + (lane >> 4)) * HH * NUD
                                 + (k + 1) * NUD + ui];
            }
            #pragma unroll
            for (int r = 0; r < 8; ++r)
                #pragma unroll
                for (int j = 0; j < 4; ++j) hp[r][j] = 0ull;
            #pragma unroll 4
            for (int i = 40; i < 64; i += 2) {         // x part
                const float* w0 = &W1s[i * W1STRIDE];
                const float* w1 = &W1s[(i + 1) * W1STRIDE];
                ulonglong2 wA = *(const ulonglong2*)&w0[4 * lane];
                ulonglong2 wB = *(const ulonglong2*)&w0[128 + 4 * lane];
                ulonglong2 wC = *(const ulonglong2*)&w1[4 * lane];
                ulonglong2 wD = *(const ulonglong2*)&w1[128 + 4 * lane];
                #pragma unroll
                for (int r = 0; r < 8; ++r) {
                    ulonglong2 zv = *(const ulonglong2*)&xd[(lr + r) * 64 + i];
                    hp[r][0] = fma2(zv.x, wA.x, hp[r][0]);
                    hp[r][1] = fma2(zv.x, wA.y, hp[r][1]);
                    hp[r][2] = fma2(zv.x, wB.x, hp[r][2]);
                    hp[r][3] = fma2(zv.x, wB.y, hp[r][3]);
                    hp[r][0] = fma2(zv.y, wC.x, hp[r][0]);
                    hp[r][1] = fma2(zv.y, wC.y, hp[r][1]);
                    hp[r][2] = fma2(zv.y, wD.x, hp[r][2]);
                    hp[r][3] = fma2(zv.y, wD.y, hp[r][3]);
                }
            }
            #pragma unroll 4
            for (int i = 64; i < 80; i += 2) {         // u part (plain + dup)
                const float* w0 = &W1s[i * W1STRIDE];
                const float* w1 = &W1s[(i + 1) * W1STRIDE];
                ulonglong2 wA = *(const ulonglong2*)&w0[4 * lane];
                ulonglong2 wB = *(const ulonglong2*)&w0[128 + 4 * lane];
                ulonglong2 wC = *(const ulonglong2*)&w1[4 * lane];
                ulonglong2 wD = *(const ulonglong2*)&w1[128 + 4 * lane];
                #pragma unroll
                for (int r = 0; r < 8; ++r) {
                    float2 uv = *(const float2*)&ubuf[r * 16 + (i - 64)];
                    ull pz0 = dup2(uv.x);
                    ull pz1 = dup2(uv.y);
                    hp[r][0] = fma2(pz0, wA.x, hp[r][0]);
                    hp[r][1] = fma2(pz0, wA.y, hp[r][1]);
                    hp[r][2] = fma2(pz0, wB.x, hp[r][2]);
                    hp[r][3] = fma2(pz0, wB.y, hp[r][3]);
                    hp[r][0] = fma2(pz1, wC.x, hp[r][0]);
                    hp[r][1] = fma2(pz1, wC.y, hp[r][1]);
                    hp[r][2] = fma2(pz1, wD.x, hp[r][2]);
                    hp[r][3] = fma2(pz1, wD.y, hp[r][3]);
                }
            }
            // write partials for rows 0-3 (E finalizes those)
            #pragma unroll
            for (int r = 0; r < 4; ++r) {
                int base = (lr + r) * 256;
                ulonglong2 s01, s23;
                s01.x = hp[r][0]; s01.y = hp[r][1];
                s23.x = hp[r][2]; s23.y = hp[r][3];
                *(ulonglong2*)&tall[base + 4 * lane]       = s01;
                *(ulonglong2*)&tall[base + 128 + 4 * lane] = s23;
            }
        }

        __syncthreads();   // sync1: partials exchanged

        // ---- finalize own 4 rows: combine + tanh; write t (tall) & gh (gall) ----
        {
            int rbase = isE ? 0 : 4;
            #pragma unroll
            for (int r = 0; r < 4; ++r) {
                int row = rbase + r;
                int base = (lr + row) * 256;
                ulonglong2 p01 = *(const ulonglong2*)&tall[base + 4 * lane];
                ulonglong2 p23 = *(const ulonglong2*)&tall[base + 128 + 4 * lane];
                ull h0 = add2(hp[row][0], p01.x);
                ull h1 = add2(hp[row][1], p01.y);
                ull h2 = add2(hp[row][2], p23.x);
                ull h3 = add2(hp[row][3], p23.y);
                ull tv[4], gv[4];
                ull hh[4] = {h0, h1, h2, h3};
                #pragma unroll
                for (int j = 0; j < 4; ++j) {
                    F2U hu; hu.u = hh[j];
                    F2U t;
                    t.f.x = tanhfast(hu.f.x);
                    t.f.y = tanhfast(hu.f.y);
                    tv[j] = t.u;
                    gv[j] = fma2(mul2(t.u, t.u), nc2p[j], c2p[j]);
                }
                ulonglong2 s01, s23;
                s01.x = tv[0]; s01.y = tv[1];
                s23.x = tv[2]; s23.y = tv[3];
                *(ulonglong2*)&tall[base + 4 * lane]       = s01;
                *(ulonglong2*)&tall[base + 128 + 4 * lane] = s23;
                s01.x = gv[0]; s01.y = gv[1];
                s23.x = gv[2]; s23.y = gv[3];
                *(ulonglong2*)&gall[base + 4 * lane]       = s01;
                *(ulonglong2*)&gall[base + 128 + 4 * lane] = s23;
            }
        }

        __syncthreads();   // sync2: t(k), gh(k) complete for all 8 rows

        if (isE) {
            // ---- E: GEMV2 all 8 rows ----
            ull acc[8][2];
            #pragma unroll
            for (int r = 0; r < 8; ++r) { acc[r][0] = 0ull; acc[r][1] = 0ull; }
            #pragma unroll 4
            for (int q = 0; q < HIDD / 4; ++q) {
                ulonglong2 wa = w2a[q];
                ulonglong2 wb = w2b[q];
                #pragma unroll
                for (int r = 0; r < 8; ++r) {
                    ulonglong2 tv =
                        *(const ulonglong2*)&tall[(lr + r) * 256 + 4 * q];
                    acc[r][0] = fma2(tv.x, wa.x, acc[r][0]);
                    acc[r][0] = fma2(tv.y, wa.y, acc[r][0]);
                    acc[r][1] = fma2(tv.x, wb.x, acc[r][1]);
                    acc[r][1] = fma2(tv.y, wb.y, acc[r][1]);
                }
            }
            #pragma unroll
            for (int r = 0; r < 8; ++r) {
                int b = b0 + r;
                F2U a0; a0.u = acc[r][0];
                F2U a1; a1.u = acc[r][1];
                float xn0 = xd[(lr + r) * 64 + lane].x
                            + 0.1f * (a0.f.x + a0.f.y);
                float xn1 = xd[(lr + r) * 64 + 32 + lane].x
                            + 0.1f * (a1.f.x + a1.f.y);
                size_t base_t = (size_t)b * (HH + 1) * NXD
                                + (size_t)(k + 1) * NXD;
                size_t base_p = (size_t)b * HH * NXD + (size_t)k * NXD;
                out_xtraj[base_t + lane]      = xn0;
                out_xtraj[base_t + 32 + lane] = xn1;
                out_xpred[base_p + lane]      = xn0;
                out_xpred[base_p + 32 + lane] = xn1;
                xd[(lr + r) * 64 + lane]      = make_float2(xn0, xn0);
                xd[(lr + r) * 64 + 32 + lane] = make_float2(xn1, xn1);
            }
        } else {
            // ---- O: grad all 8 rows (same step k) ----
            const float* gb_ = gall + lr * 256;
            ull ga[8], gb8[8], gc4[4];
            #pragma unroll
            for (int r = 0; r < 8; ++r) { ga[r] = 0ull; gb8[r] = 0ull; }
            #pragma unroll
            for (int r = 0; r < 4; ++r) gc4[r] = 0ull;

            #pragma unroll 4
            for (int q = 0; q < HIDD / 4; ++q) {
                ulonglong2 wa = wia[q];
                ulonglong2 wb = wib[q];
                ulonglong2 wc = wic[q];
                ull gl[8][2];
                #pragma unroll
                for (int r = 0; r < 8; ++r) {
                    ulonglong2 gv = *(const ulonglong2*)&gb_[r * 256 + 4 * q];
                    gl[r][0] = gv.x; gl[r][1] = gv.y;
                    ga[r]  = fma2(gv.x, wa.x, ga[r]);
                    ga[r]  = fma2(gv.y, wa.y, ga[r]);
                    gb8[r] = fma2(gv.x, wb.x, gb8[r]);
                    gb8[r] = fma2(gv.y, wb.y, gb8[r]);
                }
                #pragma unroll
                for (int r = 0; r < 4; ++r) {
                    ull s0 = lo16 ? gl[r][0] : gl[r + 4][0];
                    ull s1 = lo16 ? gl[r][1] : gl[r + 4][1];
                    gc4[r] = fma2(s0, wc.x, gc4[r]);
                    gc4[r] = fma2(s1, wc.y, gc4[r]);
                }
            }
            #pragma unroll
            for (int r = 0; r < 8; ++r) {
                int b = b0 + r;
                F2U va; va.u = ga[r];
                F2U vb; vb.u = gb8[r];
                size_t base_gx = (size_t)b * HH * NXD + (size_t)k * NXD;
                out_gx[base_gx + lane]      = 1.f + va.f.x + va.f.y;
                out_gx[base_gx + 32 + lane] = 1.f + vb.f.x + vb.f.y;
            }
            #pragma unroll
            for (int r = 0; r < 4; ++r) {
                int b = b0 + r + (lo16 ? 0 : 4);
                F2U vc; vc.u = gc4[r];
                out_gu[(size_t)b * HH * NUD + (size_t)k * NUD + ui] =
                    vc.f.x + vc.f.y;
            }
        }

        __syncthreads();   // syncA: xd updated, gall free for next step's u
    }
}

// ---------------------------------------------------------------------------
extern "C" void kernel_launch(void* const* d_in, const int* in_sizes, int n_in,
                              void* d_out, int out_size) {
    const float* x0    = (const float*)d_in[0];
    const float* W1    = (const float*)d_in[2];
    const float* b1    = (const float*)d_in[3];
    const float* W2    = (const float*)d_in[4];
    const float* noise = (const float*)d_in[5];
    const int*   nit   = (const int*)d_in[6];

    float* out = (float*)d_out;
    float* out_u     = out + OFF_U;
    float* out_xtraj = out + OFF_XTRAJ;
    float* out_xpred = out + OFF_XPRED;
    float* out_gx    = out + OFF_GX;
    float* out_gu    = out + OFF_GU;

    {
        int tot4 = BB * HH * NUD / 4;
        prep_kernel<<<(tot4 + 255) / 256, 256>>>((const float4*)noise,
                                                 nit, out_u);
    }

    const size_t smem_bytes = (size_t)SM_TOTAL_F * sizeof(float);  // 231,680
    cudaFuncSetAttribute(mpc_kernel,
                         cudaFuncAttributeMaxDynamicSharedMemorySize,
                         (int)smem_bytes);
    mpc_kernel<<<BB / 32, NT, smem_bytes>>>(x0, W1, b1, W2,
                                            out_xtraj, out_xpred,
                                            out_gx, out_gu);
}

// round 16
// speedup vs baseline: 1.1631x; 1.1631x over previous
#include <cuda_runtime.h>
#include <cstddef>

// Problem constants
#define BB    4096
#define NXD   64
#define NUD   16
#define HH    50
#define HIDD  256
#define ZD    80
#define W1STRIDE 260
#define W2STRIDE 260

// Output layout
#define OFF_U      0
#define OFF_XTRAJ  (BB*NUD)
#define OFF_XPRED  (OFF_XTRAJ + BB*(HH+1)*NXD)
#define OFF_GX     (OFF_XPRED + BB*HH*NXD)
#define OFF_GU     (OFF_GX + BB*HH*NXD)

// smem layout (float offsets). Total 57,920 floats = 231,680 B
#define SM_W1    0                        // [80][260] m-permuted
#define SM_W2T   (SM_W1 + ZD*W1STRIDE)    // [64][260] m-permuted
#define SM_XD    (SM_W2T + NXD*W2STRIDE)  // float2 [32 rows][64] dup x
#define SM_TALL  (SM_XD + 32*64*2)        // float [32 rows][256] t (u alias row lr)
#define SM_GALL  (SM_TALL + 32*256)       // float [32 rows][256] gh fp32
#define SM_TOTAL_F (SM_GALL + 32*256)

#define NT 256   // 8 warps: roll w=0..3 (8 rows each) paired with grad w+4 (same SMSP)

typedef unsigned long long ull;

__device__ float g_u9[BB * HH * NUD];

union F2U { ull u; float2 f; };

__device__ __forceinline__ ull fma2(ull a, ull b, ull c) {
    ull d;
    asm("fma.rn.f32x2 %0, %1, %2, %3;" : "=l"(d) : "l"(a), "l"(b), "l"(c));
    return d;
}
__device__ __forceinline__ ull mul2(ull a, ull b) {
    ull d;
    asm("mul.rn.f32x2 %0, %1, %2;" : "=l"(d) : "l"(a), "l"(b));
    return d;
}
// tanh(x) = 1 - 2/(exp2(2*log2e*x)+1)
__device__ __forceinline__ float tanhfast(float x) {
    float e, r;
    asm("ex2.approx.f32 %0, %1;" : "=f"(e) : "f"(x * 2.885390081777927f));
    asm("rcp.approx.f32 %0, %1;" : "=f"(r) : "f"(e + 1.0f));
    return fmaf(-2.0f, r, 1.0f);
}
// pair-local barrier: roll warp w and grad warp w+4 (same SMSP), 64 threads
#define PAIR_BAR(id) asm volatile("bar.sync %0, 64;" :: "r"(id) : "memory")

// m-permutation: lane l owns m-pairs (64j+2l, 64j+2l+1); j01/j23 groups are
// 16B-contiguous at 4l and 128+4l.
__device__ __forceinline__ int permpos(int m) {
    int j = m >> 6, l = (m & 63) >> 1, e = m & 1;
    return 128 * (j >> 1) + 4 * l + 2 * (j & 1) + e;
}

// ---------------------------------------------------------------------------
__global__ void prep_kernel(const float4* __restrict__ noise4,
                            const int* __restrict__ nit_p,
                            float* __restrict__ out_u) {
    const int TOT4 = BB * HH * NUD / 4;
    int idx = blockIdx.x * blockDim.x + threadIdx.x;
    if (idx >= TOT4) return;
    int nit = *nit_p;
    float4 s = make_float4(0.f, 0.f, 0.f, 0.f);
    for (int it = 0; it < nit - 1; ++it) {
        float4 v = noise4[(size_t)it * TOT4 + idx];
        s.x += v.x; s.y += v.y; s.z += v.z; s.w += v.w;
    }
    float4 u9 = make_float4(0.001f * s.x, 0.001f * s.y,
                            0.001f * s.z, 0.001f * s.w);
    ((float4*)g_u9)[idx] = u9;
    int base = 4 * idx;
    int rem = base % (HH * NUD);
    if (rem < NUD) {
        float4 nl = noise4[(size_t)(nit - 1) * TOT4 + idx];
        int b = base / (HH * NUD);
        float* o = out_u + b * NUD + rem;
        o[0] = u9.x + 0.001f * nl.x;
        o[1] = u9.y + 0.001f * nl.y;
        o[2] = u9.z + 0.001f * nl.z;
        o[3] = u9.w + 0.001f * nl.w;
    }
}

// ---------------------------------------------------------------------------
// grid 128 x 256. Roll warps 0-3 (8 rows each: GEMV1, tanh, GEMV2); grad
// warps 4-7 (same 8 rows: gx/gu from fp32 gh, one-step lagged within the
// step via two PAIR-LOCAL named barriers). Pair (w, w+4) shares an SMSP and
// syncs only with itself -> SMSPs drift independently, no cross-SMSP
// straggler coupling. All m-indexed smem is permuted for LDS.128/STS.128.
// ---------------------------------------------------------------------------
__global__ __launch_bounds__(NT, 1)
void mpc_kernel(const float* __restrict__ x0,
                const float* __restrict__ W1g,   // [80,256]
                const float* __restrict__ b1g,   // [256]
                const float* __restrict__ W2g,   // [256,64]
                float* __restrict__ out_xtraj,
                float* __restrict__ out_xpred,
                float* __restrict__ out_gx,
                float* __restrict__ out_gu) {
    extern __shared__ float smem[];
    float*  W1s  = smem + SM_W1;
    float*  W2Ts = smem + SM_W2T;
    float2* xd   = (float2*)(smem + SM_XD);
    float*  tall = smem + SM_TALL;
    float*  gall = smem + SM_GALL;

    const int tid = threadIdx.x;

    // ---- Stage weights (m-permuted) + c2 scratch (permuted, in tall row 0) ----
    for (int idx = tid; idx < ZD * HIDD; idx += NT) {
        int i = idx >> 8, m = idx & 255;
        W1s[i * W1STRIDE + permpos(m)] = W1g[idx];
    }
    for (int idx = tid; idx < HIDD * NXD; idx += NT) {
        int m = idx >> 6, c = idx & 63;
        W2Ts[c * W2STRIDE + permpos(m)] = W2g[idx];
    }
    {
        int m = tid;
        float s = 0.f;
        #pragma unroll 8
        for (int j = 0; j < NXD; ++j) s += W2g[m * NXD + j];
        tall[permpos(m)] = 0.1f * s;   // c2 scratch (permuted)
    }
    __syncthreads();

    const int  w    = tid >> 5, lane = tid & 31;
    const bool roll = (w < 4);
    const int  pid  = 1 + (w & 3);          // named barrier id for this pair
    const int  lr   = (w & 3) * 8;
    const int  b0   = blockIdx.x * 32 + lr;
    const int  m2   = 2 * lane;
    const int  urh  = lane >> 4, ui = lane & 15;
    const bool lo16 = (lane < 16);

    // roll constants
    ull b1p[4], c2p[4], nc2p[4];
    if (roll) {
        #pragma unroll
        for (int j = 0; j < 4; ++j) {
            b1p[j] = *(const ull*)&b1g[64 * j + m2];
            F2U c;
            c.u = *(const ull*)&tall[128 * (j >> 1) + 4 * lane + 2 * (j & 1)];
            c2p[j] = c.u;
            F2U n; n.f.x = -c.f.x; n.f.y = -c.f.y;
            nc2p[j] = n.u;
        }
    }
    __syncthreads();   // c2 scratch consumed; tall rows reusable

    if (roll) {
        // init x into xd (dup) + x_traj[:,0,:]
        #pragma unroll
        for (int r = 0; r < 8; ++r) {
            int b = b0 + r;
            float xa = x0[b * NXD + lane];
            float xb = x0[b * NXD + 32 + lane];
            xd[(lr + r) * 64 + lane]      = make_float2(xa, xa);
            xd[(lr + r) * 64 + 32 + lane] = make_float2(xb, xb);
            size_t base = (size_t)b * (HH + 1) * NXD;
            out_xtraj[base + lane]      = xa;
            out_xtraj[base + 32 + lane] = xb;
        }
        float up[4];
        #pragma unroll
        for (int v = 0; v < 4; ++v)
            up[v] = g_u9[(size_t)(b0 + 2 * v + urh) * HH * NUD + ui];

        // u staging aliases this pair's tall row lr (dup float2, [8][16])
        float2* ud = (float2*)(tall + lr * 256);
        const ulonglong2* w2a = (const ulonglong2*)&W2Ts[lane * W2STRIDE];
        const ulonglong2* w2b = (const ulonglong2*)&W2Ts[(lane + 32) * W2STRIDE];

        for (int k = 0; k < HH; ++k) {
            // ---- stage controls (dup) ----
            #pragma unroll
            for (int v = 0; v < 4; ++v)
                ud[(2 * v + urh) * 16 + ui] = make_float2(up[v], up[v]);
            __syncwarp();
            if (k + 1 < HH) {
                #pragma unroll
                for (int v = 0; v < 4; ++v)
                    up[v] = g_u9[(size_t)(b0 + 2 * v + urh) * HH * NUD
                                 + (k + 1) * NUD + ui];
            }

            // ---- GEMV1: h = z @ W1 + b1 (permuted weights, LDS.128) ----
            ull h[8][4];
            #pragma unroll
            for (int r = 0; r < 8; ++r)
                #pragma unroll
                for (int j = 0; j < 4; ++j) h[r][j] = b1p[j];

            #pragma unroll 4
            for (int i = 0; i < NXD; i += 2) {       // x part
                const float* w0 = &W1s[i * W1STRIDE];
                const float* w1 = &W1s[(i + 1) * W1STRIDE];
                ulonglong2 wA = *(const ulonglong2*)&w0[4 * lane];
                ulonglong2 wB = *(const ulonglong2*)&w0[128 + 4 * lane];
                ulonglong2 wC = *(const ulonglong2*)&w1[4 * lane];
                ulonglong2 wD = *(const ulonglong2*)&w1[128 + 4 * lane];
                #pragma unroll
                for (int r = 0; r < 8; ++r) {
                    ulonglong2 zv = *(const ulonglong2*)&xd[(lr + r) * 64 + i];
                    h[r][0] = fma2(zv.x, wA.x, h[r][0]);
                    h[r][1] = fma2(zv.x, wA.y, h[r][1]);
                    h[r][2] = fma2(zv.x, wB.x, h[r][2]);
                    h[r][3] = fma2(zv.x, wB.y, h[r][3]);
                    h[r][0] = fma2(zv.y, wC.x, h[r][0]);
                    h[r][1] = fma2(zv.y, wC.y, h[r][1]);
                    h[r][2] = fma2(zv.y, wD.x, h[r][2]);
                    h[r][3] = fma2(zv.y, wD.y, h[r][3]);
                }
            }
            #pragma unroll 4
            for (int i = NXD; i < ZD; i += 2) {      // u part (dup pairs in ud)
                const float* w0 = &W1s[i * W1STRIDE];
                const float* w1 = &W1s[(i + 1) * W1STRIDE];
                ulonglong2 wA = *(const ulonglong2*)&w0[4 * lane];
                ulonglong2 wB = *(const ulonglong2*)&w0[128 + 4 * lane];
                ulonglong2 wC = *(const ulonglong2*)&w1[4 * lane];
                ulonglong2 wD = *(const ulonglong2*)&w1[128 + 4 * lane];
                #pragma unroll
                for (int r = 0; r < 8; ++r) {
                    ulonglong2 zv =
                        *(const ulonglong2*)&ud[r * 16 + (i - NXD)];
                    h[r][0] = fma2(zv.x, wA.x, h[r][0]);
                    h[r][1] = fma2(zv.x, wA.y, h[r][1]);
                    h[r][2] = fma2(zv.x, wB.x, h[r][2]);
                    h[r][3] = fma2(zv.x, wB.y, h[r][3]);
                    h[r][0] = fma2(zv.y, wC.x, h[r][0]);
                    h[r][1] = fma2(zv.y, wC.y, h[r][1]);
                    h[r][2] = fma2(zv.y, wD.x, h[r][2]);
                    h[r][3] = fma2(zv.y, wD.y, h[r][3]);
                }
            }

            PAIR_BAR(pid);   // A: pair's grad done reading gh(k-1)

            // ---- tanh; stage t and gh (permuted, STS.128) ----
            #pragma unroll
            for (int r = 0; r < 8; ++r) {
                ull tv[4], gv[4];
                #pragma unroll
                for (int j = 0; j < 4; ++j) {
                    F2U hv; hv.u = h[r][j];
                    F2U t;
                    t.f.x = tanhfast(hv.f.x);
                    t.f.y = tanhfast(hv.f.y);
                    tv[j] = t.u;
                    gv[j] = fma2(mul2(t.u, t.u), nc2p[j], c2p[j]);
                }
                int base = (lr + r) * 256;
                ulonglong2 s01, s23;
                s01.x = tv[0]; s01.y = tv[1];
                s23.x = tv[2]; s23.y = tv[3];
                *(ulonglong2*)&tall[base + 4 * lane]       = s01;
                *(ulonglong2*)&tall[base + 128 + 4 * lane] = s23;
                s01.x = gv[0]; s01.y = gv[1];
                s23.x = gv[2]; s23.y = gv[3];
                *(ulonglong2*)&gall[base + 4 * lane]       = s01;
                *(ulonglong2*)&gall[base + 128 + 4 * lane] = s23;
            }

            PAIR_BAR(pid);   // B: t(k), gh(k) ready for pair

            // ---- GEMV2: x_next = x + 0.1 * t @ W2 (permuted m-order) ----
            ull acc[8][2];
            #pragma unroll
            for (int r = 0; r < 8; ++r) { acc[r][0] = 0ull; acc[r][1] = 0ull; }
            #pragma unroll 4
            for (int q = 0; q < HIDD / 4; ++q) {
                ulonglong2 wa = w2a[q];
                ulonglong2 wb = w2b[q];
                #pragma unroll
                for (int r = 0; r < 8; ++r) {
                    ulonglong2 tv =
                        *(const ulonglong2*)&tall[(lr + r) * 256 + 4 * q];
                    acc[r][0] = fma2(tv.x, wa.x, acc[r][0]);
                    acc[r][0] = fma2(tv.y, wa.y, acc[r][0]);
                    acc[r][1] = fma2(tv.x, wb.x, acc[r][1]);
                    acc[r][1] = fma2(tv.y, wb.y, acc[r][1]);
                }
            }
            #pragma unroll
            for (int r = 0; r < 8; ++r) {
                int b = b0 + r;
                F2U a0; a0.u = acc[r][0];
                F2U a1; a1.u = acc[r][1];
                float xn0 = xd[(lr + r) * 64 + lane].x
                            + 0.1f * (a0.f.x + a0.f.y);
                float xn1 = xd[(lr + r) * 64 + 32 + lane].x
                            + 0.1f * (a1.f.x + a1.f.y);
                size_t base_t = (size_t)b * (HH + 1) * NXD
                                + (size_t)(k + 1) * NXD;
                size_t base_p = (size_t)b * HH * NXD + (size_t)k * NXD;
                out_xtraj[base_t + lane]      = xn0;
                out_xtraj[base_t + 32 + lane] = xn1;
                out_xpred[base_p + lane]      = xn0;
                out_xpred[base_p + 32 + lane] = xn1;
                xd[(lr + r) * 64 + lane]      = make_float2(xn0, xn0);
                xd[(lr + r) * 64 + 32 + lane] = make_float2(xn1, xn1);
            }
            __syncwarp();   // intra-warp: xd/ud coherent before next step
        }
    } else {
        // ---------------- grad warps: 8 rows (same rows as pair's roll) -----
        const ulonglong2* wia = (const ulonglong2*)&W1s[lane * W1STRIDE];
        const ulonglong2* wib = (const ulonglong2*)&W1s[(32 + lane) * W1STRIDE];
        const ulonglong2* wic = (const ulonglong2*)&W1s[(64 + ui) * W1STRIDE];
        const float* gb_ = gall + lr * 256;

        for (int k = 0; k < HH; ++k) {
            PAIR_BAR(pid);   // A
            PAIR_BAR(pid);   // B: gh(k) ready

            ull ga[8], gb8[8], gc4[4];
            #pragma unroll
            for (int r = 0; r < 8; ++r) { ga[r] = 0ull; gb8[r] = 0ull; }
            #pragma unroll
            for (int r = 0; r < 4; ++r) gc4[r] = 0ull;

            #pragma unroll 4
            for (int q = 0; q < HIDD / 4; ++q) {
                ulonglong2 wa = wia[q];
                ulonglong2 wb = wib[q];
                ulonglong2 wc = wic[q];
                ull gl[8][2];
                #pragma unroll
                for (int r = 0; r < 8; ++r) {
                    ulonglong2 gv = *(const ulonglong2*)&gb_[r * 256 + 4 * q];
                    gl[r][0] = gv.x; gl[r][1] = gv.y;
                    ga[r]  = fma2(gv.x, wa.x, ga[r]);
                    ga[r]  = fma2(gv.y, wa.y, ga[r]);
                    gb8[r] = fma2(gv.x, wb.x, gb8[r]);
                    gb8[r] = fma2(gv.y, wb.y, gb8[r]);
                }
                #pragma unroll
                for (int r = 0; r < 4; ++r) {
                    ull s0 = lo16 ? gl[r][0] : gl[r + 4][0];
                    ull s1 = lo16 ? gl[r][1] : gl[r + 4][1];
                    gc4[r] = fma2(s0, wc.x, gc4[r]);
                    gc4[r] = fma2(s1, wc.y, gc4[r]);
                }
            }
            #pragma unroll
            for (int r = 0; r < 8; ++r) {
                int b = b0 + r;
                F2U va; va.u = ga[r];
                F2U vb; vb.u = gb8[r];
                size_t base_gx = (size_t)b * HH * NXD + (size_t)k * NXD;
                out_gx[base_gx + lane]      = 1.f + va.f.x + va.f.y;
                out_gx[base_gx + 32 + lane] = 1.f + vb.f.x + vb.f.y;
            }
            #pragma unroll
            for (int r = 0; r < 4; ++r) {
                int b = b0 + r + (lo16 ? 0 : 4);
                F2U vc; vc.u = gc4[r];
                out_gu[(size_t)b * HH * NUD + (size_t)k * NUD + ui] =
                    vc.f.x + vc.f.y;
            }
        }
    }
}

// ---------------------------------------------------------------------------
extern "C" void kernel_launch(void* const* d_in, const int* in_sizes, int n_in,
                              void* d_out, int out_size) {
    const float* x0    = (const float*)d_in[0];
    const float* W1    = (const float*)d_in[2];
    const float* b1    = (const float*)d_in[3];
    const float* W2    = (const float*)d_in[4];
    const float* noise = (const float*)d_in[5];
    const int*   nit   = (const int*)d_in[6];

    float* out = (float*)d_out;
    float* out_u     = out + OFF_U;
    float* out_xtraj = out + OFF_XTRAJ;
    float* out_xpred = out + OFF_XPRED;
    float* out_gx    = out + OFF_GX;
    float* out_gu    = out + OFF_GU;

    {
        int tot4 = BB * HH * NUD / 4;
        prep_kernel<<<(tot4 + 255) / 256, 256>>>((const float4*)noise,
                                                 nit, out_u);
    }

    const size_t smem_bytes = (size_t)SM_TOTAL_F * sizeof(float);  // 231,680
    cudaFuncSetAttribute(mpc_kernel,
                         cudaFuncAttributeMaxDynamicSharedMemorySize,
                         (int)smem_bytes);
    mpc_kernel<<<BB / 32, NT, smem_bytes>>>(x0, W1, b1, W2,
                                            out_xtraj, out_xpred,
                                            out_gx, out_gu);
}